// round 1
// baseline (speedup 1.0000x reference)
#include <cuda_runtime.h>
#include <string.h>

#define LEAK 0.1f
#define BN_EPSF 1e-5f

// problem dims (fixed by the dataset)
#define BB     16
#define NWAY   5
#define NSHOT  5
#define NQ     150
#define CC     64
#define HH     5
#define WW     5
#define HWSZ   25
#define NSAMP_Q (BB*NQ)        // 2400
#define NSAMP_P (BB*NWAY)      // 80
#define NPAIR  (NSAMP_Q*NWAY)  // 12000
#define NHID   300

// ---------------- scratch (device globals; no allocation allowed) -----------
__device__ float  g_protos[NSAMP_P * CC * HWSZ];          // 80 x 1600
__device__ float2 g_wq2[CC * 9 * 32];                     // [ic][tap][ocp] scaled, oc-pair packed
__device__ float2 g_wp2[CC * 9 * 32];
__device__ float2 g_shift2[32];
__device__ float2 g_cp[NSAMP_P * 32 * HWSZ];              // proto conv out (scaled + shifted), pair-packed
__device__ float  g_feat[NPAIR * CC];                     // pooled features

// ---------------- packed f32x2 FMA (2x fp32 throughput on sm_100) -----------
__device__ __forceinline__ float2 ffma2(float2 a, float2 b, float2 c) {
    unsigned long long A, B, C, D;
    memcpy(&A, &a, 8); memcpy(&B, &b, 8); memcpy(&C, &c, 8);
    asm("fma.rn.f32x2 %0, %1, %2, %3;" : "=l"(D) : "l"(A), "l"(B), "l"(C));
    float2 d; memcpy(&d, &D, 8);
    return d;
}

// ---------------- K0: BN fold + weight repack --------------------------------
// wq2[ic][k][ocp] = ( w[2ocp][ic][k]*scale[2ocp], w[2ocp+1][ic][k]*scale[2ocp+1] )
// wp2 same but input channels 64..127. shift2[ocp] = BN shift pair.
__global__ void prep_kernel(const float* __restrict__ cw,
                            const float* __restrict__ gamma,
                            const float* __restrict__ beta,
                            const float* __restrict__ mean,
                            const float* __restrict__ var) {
    int gid = blockIdx.x * blockDim.x + threadIdx.x;
    const int total = CC * 9 * 32;  // 18432
    if (gid < 2 * total) {
        int half = gid / total;
        int idx  = gid % total;
        int ic   = idx / (9 * 32);
        int k    = (idx / 32) % 9;
        int ocp  = idx & 31;
        int icf  = ic + half * 64;
        int oc0 = 2 * ocp, oc1 = oc0 + 1;
        float s0 = gamma[oc0] * rsqrtf(var[oc0] + BN_EPSF);
        float s1 = gamma[oc1] * rsqrtf(var[oc1] + BN_EPSF);
        float2 wv = make_float2(cw[(oc0 * 128 + icf) * 9 + k] * s0,
                                cw[(oc1 * 128 + icf) * 9 + k] * s1);
        if (half) g_wp2[idx] = wv; else g_wq2[idx] = wv;
    }
    if (gid < 32) {
        int oc0 = 2 * gid, oc1 = oc0 + 1;
        float s0 = gamma[oc0] * rsqrtf(var[oc0] + BN_EPSF);
        float s1 = gamma[oc1] * rsqrtf(var[oc1] + BN_EPSF);
        g_shift2[gid] = make_float2(beta[oc0] - mean[oc0] * s0,
                                    beta[oc1] - mean[oc1] * s1);
    }
}

// ---------------- K1: protos = mean of 10 supports ---------------------------
__global__ void protos_kernel(const float* __restrict__ shot,
                              const float* __restrict__ pseudo) {
    int s = blockIdx.x;                 // b*5 + way
    int base = s * NSHOT * CC * HWSZ;   // [(b*5+w)*5 + k]*1600
    for (int i = threadIdx.x; i < CC * HWSZ; i += blockDim.x) {
        float a = 0.f;
        #pragma unroll
        for (int k = 0; k < NSHOT; k++) a += shot[base + k * CC * HWSZ + i];
        #pragma unroll
        for (int k = 0; k < NSHOT; k++) a += pseudo[base + k * CC * HWSZ + i];
        g_protos[s * CC * HWSZ + i] = a * 0.1f;
    }
}

// ---------------- conv core: one sample, 3x3 SAME, 64->64, pair-packed -------
// thread (ocp = tid&31, ox = tid>>5) accumulates acc[oy] (float2 = oc pair)
__device__ __forceinline__ void conv_accum(const float* xs, const float2* __restrict__ wg,
                                           int ocp, int ox, float2 acc[5]) {
    #pragma unroll 1
    for (int ic = 0; ic < CC; ic++) {
        const float* xr = xs + ic * HWSZ;
        float v[5][3];
        #pragma unroll
        for (int iy = 0; iy < 5; iy++) {
            #pragma unroll
            for (int dx = 0; dx < 3; dx++) {
                int ix = ox - 1 + dx;
                v[iy][dx] = (ix >= 0 && ix < 5) ? xr[iy * 5 + ix] : 0.f;
            }
        }
        const float2* wr = wg + ic * 9 * 32 + ocp;
        float2 w[9];
        #pragma unroll
        for (int k = 0; k < 9; k++) w[k] = wr[k * 32];
        #pragma unroll
        for (int oy = 0; oy < 5; oy++) {
            #pragma unroll
            for (int ky = 0; ky < 3; ky++) {
                int iy = oy + ky - 1;
                if (iy >= 0 && iy < 5) {
                    #pragma unroll
                    for (int kx = 0; kx < 3; kx++) {
                        float vv = v[iy][kx];
                        acc[oy] = ffma2(w[ky * 3 + kx], make_float2(vv, vv), acc[oy]);
                    }
                }
            }
        }
    }
}

// ---------------- K2: conv on protos (80 samples), +BN shift -----------------
__global__ void __launch_bounds__(160) convp_kernel() {
    __shared__ float xs[CC * HWSZ];
    int s = blockIdx.x;
    int tid = threadIdx.x;
    const float* src = g_protos + s * CC * HWSZ;
    for (int i = tid; i < CC * HWSZ; i += 160) xs[i] = src[i];
    __syncthreads();
    int ocp = tid & 31, ox = tid >> 5;
    float2 acc[5] = {};
    conv_accum(xs, g_wp2, ocp, ox, acc);
    float2 sh = g_shift2[ocp];
    float2* dst = g_cp + (s * 32 + ocp) * HWSZ;
    #pragma unroll
    for (int oy = 0; oy < 5; oy++) {
        float2 t = acc[oy];
        t.x += sh.x; t.y += sh.y;
        dst[oy * 5 + ox] = t;
    }
}

// ---------------- K3: conv on queries + combine per way + leaky + pool -------
__global__ void __launch_bounds__(160) convq_kernel(const float* __restrict__ xq) {
    __shared__ float xs[CC * HWSZ];
    __shared__ float2 red[160];
    int s = blockIdx.x;                 // 0..2399 = b*150 + q
    int tid = threadIdx.x;
    const float* src = xq + s * CC * HWSZ;
    for (int i = tid; i < CC * HWSZ; i += 160) xs[i] = src[i];
    __syncthreads();
    int ocp = tid & 31, ox = tid >> 5;
    float2 acc[5] = {};
    conv_accum(xs, g_wq2, ocp, ox, acc);

    int b = s / NQ;
    for (int w = 0; w < NWAY; w++) {
        const float2* cp = g_cp + ((b * NWAY + w) * 32 + ocp) * HWSZ;
        float2 ps = make_float2(0.f, 0.f);
        #pragma unroll
        for (int oy = 0; oy < 5; oy++) {
            float2 t = cp[oy * 5 + ox];
            t.x += acc[oy].x; t.y += acc[oy].y;
            t.x = fmaxf(t.x, LEAK * t.x);
            t.y = fmaxf(t.y, LEAK * t.y);
            ps.x += t.x; ps.y += t.y;
        }
        red[tid] = ps;
        __syncthreads();
        if (tid < 32) {
            float2 a0 = red[tid],      a1 = red[tid + 32], a2 = red[tid + 64];
            float2 a3 = red[tid + 96], a4 = red[tid + 128];
            float fx = (a0.x + a1.x + a2.x + a3.x + a4.x) * (1.f / 25.f);
            float fy = (a0.y + a1.y + a2.y + a3.y + a4.y) * (1.f / 25.f);
            float2* fo = (float2*)(g_feat + (s * NWAY + w) * CC);
            fo[tid] = make_float2(fx, fy);
        }
        __syncthreads();
    }
}

// ---------------- K4: relation MLP 64->300->1 + sigmoid ----------------------
__global__ void __launch_bounds__(320) mlp_kernel(const float* __restrict__ w1,
                                                  const float* __restrict__ b1,
                                                  const float* __restrict__ w2,
                                                  const float* __restrict__ b2,
                                                  float* __restrict__ out) {
    __shared__ __align__(16) float fsT[64][16];   // transposed feature tile (16 rows)
    __shared__ float2 wsum[10][8];
    int s0 = blockIdx.x * 16;
    int tid = threadIdx.x;
    for (int i = tid; i < 16 * 64; i += 320) {
        int r = i >> 6, c = i & 63;
        fsT[c][r] = g_feat[(s0 + r) * CC + c];
    }
    __syncthreads();

    float2 po[8];
    #pragma unroll
    for (int rp = 0; rp < 8; rp++) po[rp] = make_float2(0.f, 0.f);

    if (tid < NHID) {
        int j = tid;
        float2 acc[8];
        #pragma unroll
        for (int rp = 0; rp < 8; rp++) acc[rp] = make_float2(0.f, 0.f);
        #pragma unroll 4
        for (int k = 0; k < 64; k++) {
            float wv = w1[k * NHID + j];
            float2 wv2 = make_float2(wv, wv);
            const float2* fr = (const float2*)fsT[k];
            #pragma unroll
            for (int rp = 0; rp < 8; rp++)
                acc[rp] = ffma2(fr[rp], wv2, acc[rp]);
        }
        float bj = b1[j], w2j = w2[j];
        #pragma unroll
        for (int rp = 0; rp < 8; rp++) {
            float hx = acc[rp].x + bj; hx = fmaxf(hx, LEAK * hx);
            float hy = acc[rp].y + bj; hy = fmaxf(hy, LEAK * hy);
            po[rp] = make_float2(hx * w2j, hy * w2j);
        }
    }
    // reduce po over all threads
    #pragma unroll
    for (int off = 16; off; off >>= 1) {
        #pragma unroll
        for (int rp = 0; rp < 8; rp++) {
            po[rp].x += __shfl_down_sync(0xffffffffu, po[rp].x, off);
            po[rp].y += __shfl_down_sync(0xffffffffu, po[rp].y, off);
        }
    }
    int wid = tid >> 5, lid = tid & 31;
    if (lid == 0) {
        #pragma unroll
        for (int rp = 0; rp < 8; rp++) wsum[wid][rp] = po[rp];
    }
    __syncthreads();
    if (tid < 16) {
        int rp = tid >> 1, half = tid & 1;
        float a = 0.f;
        #pragma unroll
        for (int w = 0; w < 10; w++)
            a += half ? wsum[w][rp].y : wsum[w][rp].x;
        a += b2[0];
        out[s0 + tid] = 1.f / (1.f + expf(-a));
    }
}

// ---------------- launch -----------------------------------------------------
extern "C" void kernel_launch(void* const* d_in, const int* in_sizes, int n_in,
                              void* d_out, int out_size) {
    const float* x_shot   = (const float*)d_in[0];
    const float* x_pseudo = (const float*)d_in[1];
    const float* x_query  = (const float*)d_in[2];
    const float* conv_w   = (const float*)d_in[3];
    const float* bn_gamma = (const float*)d_in[4];
    const float* bn_beta  = (const float*)d_in[5];
    const float* bn_mean  = (const float*)d_in[6];
    const float* bn_var   = (const float*)d_in[7];
    const float* w1       = (const float*)d_in[8];
    const float* b1       = (const float*)d_in[9];
    const float* w2       = (const float*)d_in[10];
    const float* b2       = (const float*)d_in[11];
    float* out = (float*)d_out;

    prep_kernel<<<(2 * CC * 9 * 32 + 255) / 256, 256>>>(conv_w, bn_gamma, bn_beta, bn_mean, bn_var);
    protos_kernel<<<NSAMP_P, 256>>>(x_shot, x_pseudo);
    convp_kernel<<<NSAMP_P, 160>>>();
    convq_kernel<<<NSAMP_Q, 160>>>(x_query);
    mlp_kernel<<<NPAIR / 16, 320>>>(w1, b1, w2, b2, out);
}

// round 2
// speedup vs baseline: 1.1336x; 1.1336x over previous
#include <cuda_runtime.h>
#include <string.h>

#define LEAK 0.1f
#define BN_EPSF 1e-5f

#define BB     16
#define NWAY   5
#define NSHOT  5
#define NQ     150
#define CC     64
#define HWSZ   25
#define NSAMP_Q (BB*NQ)        // 2400
#define NSAMP_P (BB*NWAY)      // 80
#define NPAIR  (NSAMP_Q*NWAY)  // 12000
#define NHID   300

// ---------------- scratch ----------------------------------------------------
__device__ float  g_protos[NSAMP_P * CC * HWSZ];          // 80 x 1600
__device__ float2 g_wq2[CC * 9 * 32];                     // [ic][tap][ocp], BN-scaled, oc-pair packed
__device__ float2 g_wp2[CC * 9 * 32];
__device__ float2 g_shift2[32];
__device__ float2 g_cp[NSAMP_P * HWSZ * 32];              // proto conv out, layout [samp][pix][ocp]
__device__ float  g_feat[NPAIR * CC];                     // pooled features

// ---------------- packed f32x2 FMA -------------------------------------------
__device__ __forceinline__ float2 ffma2(float2 a, float2 b, float2 c) {
    unsigned long long A, B, C, D;
    memcpy(&A, &a, 8); memcpy(&B, &b, 8); memcpy(&C, &c, 8);
    asm("fma.rn.f32x2 %0, %1, %2, %3;" : "=l"(D) : "l"(A), "l"(B), "l"(C));
    float2 d; memcpy(&d, &D, 8);
    return d;
}

// ---------------- K0: prep (BN fold + repack) fused with protos mean ---------
#define PREP_BLOCKS 145   // 145*256 = 37120 >= 36864
#define PROTO_BLOCKS 125  // 125*256 = 32000 float4 items
__global__ void prep_protos_kernel(const float* __restrict__ cw,
                                   const float* __restrict__ gamma,
                                   const float* __restrict__ beta,
                                   const float* __restrict__ mean,
                                   const float* __restrict__ var,
                                   const float* __restrict__ shot,
                                   const float* __restrict__ pseudo) {
    int bid = blockIdx.x;
    int tid = threadIdx.x;
    if (bid < PREP_BLOCKS) {
        int gid = bid * 256 + tid;
        const int total = CC * 9 * 32;  // 18432
        if (gid < 2 * total) {
            int half = gid / total;
            int idx  = gid % total;
            int ic   = idx / (9 * 32);
            int k    = (idx / 32) % 9;
            int ocp  = idx & 31;
            int icf  = ic + half * 64;
            int oc0 = 2 * ocp, oc1 = oc0 + 1;
            float s0 = gamma[oc0] * rsqrtf(var[oc0] + BN_EPSF);
            float s1 = gamma[oc1] * rsqrtf(var[oc1] + BN_EPSF);
            float2 wv = make_float2(cw[(oc0 * 128 + icf) * 9 + k] * s0,
                                    cw[(oc1 * 128 + icf) * 9 + k] * s1);
            if (half) g_wp2[idx] = wv; else g_wq2[idx] = wv;
        }
        if (gid < 32) {
            int oc0 = 2 * gid, oc1 = oc0 + 1;
            float s0 = gamma[oc0] * rsqrtf(var[oc0] + BN_EPSF);
            float s1 = gamma[oc1] * rsqrtf(var[oc1] + BN_EPSF);
            g_shift2[gid] = make_float2(beta[oc0] - mean[oc0] * s0,
                                        beta[oc1] - mean[oc1] * s1);
        }
    } else {
        int pid = (bid - PREP_BLOCKS) * 256 + tid;  // float4 item
        if (pid < NSAMP_P * 400) {
            int s = pid / 400;
            int j = pid - s * 400;
            const float4* sh = (const float4*)(shot   + (size_t)s * NSHOT * 1600) + j;
            const float4* ps = (const float4*)(pseudo + (size_t)s * NSHOT * 1600) + j;
            float4 a = make_float4(0.f, 0.f, 0.f, 0.f);
            #pragma unroll
            for (int k = 0; k < NSHOT; k++) {
                float4 v = sh[k * 400];
                a.x += v.x; a.y += v.y; a.z += v.z; a.w += v.w;
            }
            #pragma unroll
            for (int k = 0; k < NSHOT; k++) {
                float4 v = ps[k * 400];
                a.x += v.x; a.y += v.y; a.z += v.z; a.w += v.w;
            }
            a.x *= 0.1f; a.y *= 0.1f; a.z *= 0.1f; a.w *= 0.1f;
            ((float4*)g_protos)[pid] = a;
        }
    }
}

// ---------------- conv core: templated on ox (warp-uniform), NS samples ------
// xs layout per sample: [ic][iy][8 floats]: col0=0 pad, cols1..5 = x, col6,7=0
template<int OX, int NS>
__device__ __forceinline__ void conv_core(const float* xs, const float2* __restrict__ wg,
                                          int ocp, float2 (&acc)[NS][5]) {
    #pragma unroll 1
    for (int ic = 0; ic < CC; ic++) {
        const float2* wr = wg + ic * 288 + ocp;
        float2 w[9];
        #pragma unroll
        for (int k = 0; k < 9; k++) w[k] = wr[k * 32];
        #pragma unroll
        for (int s = 0; s < NS; s++) {
            const float4* rb = (const float4*)(xs + s * 2560 + ic * 40);
            #pragma unroll
            for (int iy = 0; iy < 5; iy++) {
                float v0, v1, v2;
                if (OX == 0) { float4 a = rb[iy * 2];     v0 = a.x; v1 = a.y; v2 = a.z; }
                if (OX == 1) { float4 a = rb[iy * 2];     v0 = a.y; v1 = a.z; v2 = a.w; }
                if (OX == 2) { float4 a = rb[iy * 2]; float4 b = rb[iy * 2 + 1];
                               v0 = a.z; v1 = a.w; v2 = b.x; }
                if (OX == 3) { float4 a = rb[iy * 2]; float4 b = rb[iy * 2 + 1];
                               v0 = a.w; v1 = b.x; v2 = b.y; }
                if (OX == 4) { float4 b = rb[iy * 2 + 1]; v0 = b.x; v1 = b.y; v2 = b.z; }
                #pragma unroll
                for (int oy = 0; oy < 5; oy++) {
                    int ky = iy - oy + 1;
                    if (ky >= 0 && ky <= 2) {
                        acc[s][oy] = ffma2(w[ky * 3 + 0], make_float2(v0, v0), acc[s][oy]);
                        acc[s][oy] = ffma2(w[ky * 3 + 1], make_float2(v1, v1), acc[s][oy]);
                        acc[s][oy] = ffma2(w[ky * 3 + 2], make_float2(v2, v2), acc[s][oy]);
                    }
                }
            }
        }
    }
}

// ---------------- K1: conv on protos (80 blocks, 1 sample each) -------------
__global__ void __launch_bounds__(160) convp_kernel() {
    __shared__ __align__(16) float buf[2560];
    int tid = threadIdx.x;
    int s = blockIdx.x;
    for (int d4 = tid; d4 < 640; d4 += 160) {
        int row = d4 >> 1, half = d4 & 1;
        const float* src = g_protos + (size_t)s * 1600 + row * 5;
        float4 v = half ? make_float4(src[3], src[4], 0.f, 0.f)
                        : make_float4(0.f, src[0], src[1], src[2]);
        ((float4*)buf)[d4] = v;
    }
    __syncthreads();
    int ocp = tid & 31, warp = tid >> 5;
    float2 acc[1][5];
    #pragma unroll
    for (int i = 0; i < 5; i++) acc[0][i] = make_float2(0.f, 0.f);
    switch (warp) {
        case 0: conv_core<0, 1>(buf, g_wp2, ocp, acc); break;
        case 1: conv_core<1, 1>(buf, g_wp2, ocp, acc); break;
        case 2: conv_core<2, 1>(buf, g_wp2, ocp, acc); break;
        case 3: conv_core<3, 1>(buf, g_wp2, ocp, acc); break;
        default: conv_core<4, 1>(buf, g_wp2, ocp, acc); break;
    }
    float2 sh = g_shift2[ocp];
    #pragma unroll
    for (int oy = 0; oy < 5; oy++) {
        float2 t = acc[0][oy];
        t.x += sh.x; t.y += sh.y;
        g_cp[(s * 25 + oy * 5 + warp) * 32 + ocp] = t;   // [samp][pix][ocp]
    }
}

// ---------------- K2: conv on queries (4/block) + combine + leaky + pool -----
__global__ void __launch_bounds__(160, 4) convq_kernel(const float* __restrict__ xq) {
    __shared__ __align__(16) float buf[4 * 2560];        // 40 KB, reused as acc buffer
    int tid = threadIdx.x;
    int s0 = blockIdx.x * 4;

    // load 4 samples, padded rows of 8
    for (int d4 = tid; d4 < 2560; d4 += 160) {
        int row = d4 >> 1, half = d4 & 1;     // row = s*320 + ic*5 + iy
        int s = row / 320;
        int r2 = row - s * 320;
        const float* src = xq + (size_t)(s0 + s) * 1600 + r2 * 5;
        float4 v = half ? make_float4(src[3], src[4], 0.f, 0.f)
                        : make_float4(0.f, src[0], src[1], src[2]);
        ((float4*)buf)[d4] = v;
    }
    __syncthreads();

    int ocp = tid & 31, warp = tid >> 5;     // warp = ox
    float2 acc[4][5];
    #pragma unroll
    for (int s = 0; s < 4; s++)
        #pragma unroll
        for (int i = 0; i < 5; i++) acc[s][i] = make_float2(0.f, 0.f);
    switch (warp) {
        case 0: conv_core<0, 4>(buf, g_wq2, ocp, acc); break;
        case 1: conv_core<1, 4>(buf, g_wq2, ocp, acc); break;
        case 2: conv_core<2, 4>(buf, g_wq2, ocp, acc); break;
        case 3: conv_core<3, 4>(buf, g_wq2, ocp, acc); break;
        default: conv_core<4, 4>(buf, g_wq2, ocp, acc); break;
    }
    __syncthreads();   // everyone done reading buf

    // transpose acc into smem: [s][pix][ocp] float2
    float2* sm_acc = (float2*)buf;
    #pragma unroll
    for (int s = 0; s < 4; s++)
        #pragma unroll
        for (int oy = 0; oy < 5; oy++)
            sm_acc[(s * 25 + oy * 5 + warp) * 32 + ocp] = acc[s][oy];
    __syncthreads();

    // epilogue: 640 items = (s in 0..3) x (way) x (ocp)
    for (int it = tid; it < 640; it += 160) {
        int oc = it & 31;
        int sw = it >> 5;                 // 0..19
        int s  = sw / 5;
        int w  = sw - s * 5;
        int samp = s0 + s;
        int b = samp / NQ;
        const float2* cp = g_cp + ((b * 5 + w) * 25) * 32 + oc;
        const float2* qa = sm_acc + (s * 25) * 32 + oc;
        float ax = 0.f, ay = 0.f;
        #pragma unroll
        for (int p = 0; p < 25; p++) {
            float2 t = qa[p * 32];
            float2 c = cp[p * 32];
            float x = t.x + c.x; x = fmaxf(x, LEAK * x);
            float y = t.y + c.y; y = fmaxf(y, LEAK * y);
            ax += x; ay += y;
        }
        ((float2*)g_feat)[(samp * 5 + w) * 32 + oc] = make_float2(ax * 0.04f, ay * 0.04f);
    }
}

// ---------------- K3: relation MLP 64->300->1 + sigmoid ----------------------
__global__ void __launch_bounds__(320) mlp_kernel(const float* __restrict__ w1,
                                                  const float* __restrict__ b1,
                                                  const float* __restrict__ w2,
                                                  const float* __restrict__ b2,
                                                  float* __restrict__ out) {
    __shared__ __align__(16) float fsT[64][16];
    __shared__ float2 wsum[10][8];
    int s0 = blockIdx.x * 16;
    int tid = threadIdx.x;
    for (int i = tid; i < 16 * 64; i += 320) {
        int r = i >> 6, c = i & 63;
        fsT[c][r] = g_feat[(s0 + r) * CC + c];
    }
    __syncthreads();

    float2 po[8];
    #pragma unroll
    for (int rp = 0; rp < 8; rp++) po[rp] = make_float2(0.f, 0.f);

    if (tid < NHID) {
        int j = tid;
        float2 acc[8];
        #pragma unroll
        for (int rp = 0; rp < 8; rp++) acc[rp] = make_float2(0.f, 0.f);
        #pragma unroll 4
        for (int k = 0; k < 64; k++) {
            float wv = w1[k * NHID + j];
            float2 wv2 = make_float2(wv, wv);
            const float2* fr = (const float2*)fsT[k];
            #pragma unroll
            for (int rp = 0; rp < 8; rp++)
                acc[rp] = ffma2(fr[rp], wv2, acc[rp]);
        }
        float bj = b1[j], w2j = w2[j];
        #pragma unroll
        for (int rp = 0; rp < 8; rp++) {
            float hx = acc[rp].x + bj; hx = fmaxf(hx, LEAK * hx);
            float hy = acc[rp].y + bj; hy = fmaxf(hy, LEAK * hy);
            po[rp] = make_float2(hx * w2j, hy * w2j);
        }
    }
    #pragma unroll
    for (int off = 16; off; off >>= 1) {
        #pragma unroll
        for (int rp = 0; rp < 8; rp++) {
            po[rp].x += __shfl_down_sync(0xffffffffu, po[rp].x, off);
            po[rp].y += __shfl_down_sync(0xffffffffu, po[rp].y, off);
        }
    }
    int wid = tid >> 5, lid = tid & 31;
    if (lid == 0) {
        #pragma unroll
        for (int rp = 0; rp < 8; rp++) wsum[wid][rp] = po[rp];
    }
    __syncthreads();
    if (tid < 16) {
        int rp = tid >> 1, half = tid & 1;
        float a = 0.f;
        #pragma unroll
        for (int w = 0; w < 10; w++)
            a += half ? wsum[w][rp].y : wsum[w][rp].x;
        a += b2[0];
        out[s0 + tid] = 1.f / (1.f + expf(-a));
    }
}

// ---------------- launch -----------------------------------------------------
extern "C" void kernel_launch(void* const* d_in, const int* in_sizes, int n_in,
                              void* d_out, int out_size) {
    const float* x_shot   = (const float*)d_in[0];
    const float* x_pseudo = (const float*)d_in[1];
    const float* x_query  = (const float*)d_in[2];
    const float* conv_w   = (const float*)d_in[3];
    const float* bn_gamma = (const float*)d_in[4];
    const float* bn_beta  = (const float*)d_in[5];
    const float* bn_mean  = (const float*)d_in[6];
    const float* bn_var   = (const float*)d_in[7];
    const float* w1       = (const float*)d_in[8];
    const float* b1       = (const float*)d_in[9];
    const float* w2       = (const float*)d_in[10];
    const float* b2       = (const float*)d_in[11];
    float* out = (float*)d_out;

    prep_protos_kernel<<<PREP_BLOCKS + PROTO_BLOCKS, 256>>>(
        conv_w, bn_gamma, bn_beta, bn_mean, bn_var, x_shot, x_pseudo);
    convp_kernel<<<NSAMP_P, 160>>>();
    convq_kernel<<<NSAMP_Q / 4, 160>>>(x_query);
    mlp_kernel<<<NPAIR / 16, 320>>>(w1, b1, w2, b2, out);
}

// round 3
// speedup vs baseline: 1.2613x; 1.1127x over previous
#include <cuda_runtime.h>
#include <string.h>

#define LEAK 0.1f
#define BN_EPSF 1e-5f

#define BB     16
#define NWAY   5
#define NSHOT  5
#define NQ     150
#define CC     64
#define HWSZ   25
#define NSAMP_Q (BB*NQ)        // 2400
#define NSAMP_P (BB*NWAY)      // 80
#define NPAIR  (NSAMP_Q*NWAY)  // 12000
#define NHID   300

// ---------------- scratch ----------------------------------------------------
__device__ float  g_protos[NSAMP_P * CC * HWSZ];
__device__ __align__(16) float2 g_wq2[CC * 9 * 32];   // [ic][tap][ocp], BN-scaled, oc-pair packed
__device__ __align__(16) float2 g_wp2[CC * 9 * 32];
__device__ float2 g_shift2[32];
__device__ float2 g_cp[NSAMP_P * HWSZ * 32];          // proto conv out [samp][pix][ocp]
__device__ float  g_feat[NPAIR * CC];

// ---------------- packed f32x2 FMA -------------------------------------------
__device__ __forceinline__ float2 ffma2(float2 a, float2 b, float2 c) {
    unsigned long long A, B, C, D;
    memcpy(&A, &a, 8); memcpy(&B, &b, 8); memcpy(&C, &c, 8);
    asm("fma.rn.f32x2 %0, %1, %2, %3;" : "=l"(D) : "l"(A), "l"(B), "l"(C));
    float2 d; memcpy(&d, &D, 8);
    return d;
}

// ---------------- K0: prep (BN fold + repack) fused with protos mean ---------
#define PREP_BLOCKS 145
#define PROTO_BLOCKS 125
__global__ void prep_protos_kernel(const float* __restrict__ cw,
                                   const float* __restrict__ gamma,
                                   const float* __restrict__ beta,
                                   const float* __restrict__ mean,
                                   const float* __restrict__ var,
                                   const float* __restrict__ shot,
                                   const float* __restrict__ pseudo) {
    int bid = blockIdx.x;
    int tid = threadIdx.x;
    if (bid < PREP_BLOCKS) {
        int gid = bid * 256 + tid;
        const int total = CC * 9 * 32;  // 18432
        if (gid < 2 * total) {
            int half = gid / total;
            int idx  = gid % total;
            int ic   = idx / (9 * 32);
            int k    = (idx / 32) % 9;
            int ocp  = idx & 31;
            int icf  = ic + half * 64;
            int oc0 = 2 * ocp, oc1 = oc0 + 1;
            float s0 = gamma[oc0] * rsqrtf(var[oc0] + BN_EPSF);
            float s1 = gamma[oc1] * rsqrtf(var[oc1] + BN_EPSF);
            float2 wv = make_float2(cw[(oc0 * 128 + icf) * 9 + k] * s0,
                                    cw[(oc1 * 128 + icf) * 9 + k] * s1);
            if (half) g_wp2[idx] = wv; else g_wq2[idx] = wv;
        }
        if (gid < 32) {
            int oc0 = 2 * gid, oc1 = oc0 + 1;
            float s0 = gamma[oc0] * rsqrtf(var[oc0] + BN_EPSF);
            float s1 = gamma[oc1] * rsqrtf(var[oc1] + BN_EPSF);
            g_shift2[gid] = make_float2(beta[oc0] - mean[oc0] * s0,
                                        beta[oc1] - mean[oc1] * s1);
        }
    } else {
        int pid = (bid - PREP_BLOCKS) * 256 + tid;
        if (pid < NSAMP_P * 400) {
            int s = pid / 400;
            int j = pid - s * 400;
            const float4* sh = (const float4*)(shot   + (size_t)s * NSHOT * 1600) + j;
            const float4* ps = (const float4*)(pseudo + (size_t)s * NSHOT * 1600) + j;
            float4 a = make_float4(0.f, 0.f, 0.f, 0.f);
            #pragma unroll
            for (int k = 0; k < NSHOT; k++) {
                float4 v = sh[k * 400];
                a.x += v.x; a.y += v.y; a.z += v.z; a.w += v.w;
            }
            #pragma unroll
            for (int k = 0; k < NSHOT; k++) {
                float4 v = ps[k * 400];
                a.x += v.x; a.y += v.y; a.z += v.z; a.w += v.w;
            }
            a.x *= 0.1f; a.y *= 0.1f; a.z *= 0.1f; a.w *= 0.1f;
            ((float4*)g_protos)[pid] = a;
        }
    }
}

// ---------------- conv inner: one ic, exact taps, acc[25] --------------------
// w[9] = taps for this lane's oc-pair; xr -> 25-float channel (warp-uniform)
__device__ __forceinline__ void conv_ic(const float* __restrict__ xr,
                                        const float2 w[9], float2 acc[25]) {
    #pragma unroll
    for (int iy = 0; iy < 5; iy++) {
        float v0 = xr[iy * 5 + 0], v1 = xr[iy * 5 + 1], v2 = xr[iy * 5 + 2];
        float v3 = xr[iy * 5 + 3], v4 = xr[iy * 5 + 4];
        float xv[5] = {v0, v1, v2, v3, v4};
        #pragma unroll
        for (int oy = 0; oy < 5; oy++) {
            int ky = iy - oy + 1;
            if (ky >= 0 && ky <= 2) {
                #pragma unroll
                for (int ox = 0; ox < 5; ox++) {
                    #pragma unroll
                    for (int kx = 0; kx < 3; kx++) {
                        int j = ox - 1 + kx;
                        if (j >= 0 && j < 5) {
                            float v = xv[j];
                            acc[oy * 5 + ox] =
                                ffma2(w[ky * 3 + kx], make_float2(v, v), acc[oy * 5 + ox]);
                        }
                    }
                }
            }
        }
    }
}

// ---------------- K1: conv on protos, 4-way ic split per sample --------------
// block = 256 threads = 8 warps = 2 samples x 4 ic-chunks; grid 40
__global__ void __launch_bounds__(256) convp_kernel() {
    __shared__ float2 red[2 * HWSZ * 32];    // 12.8 KB
    int tid = threadIdx.x;
    int lane = tid & 31;
    int warp = tid >> 5;
    int sl = warp >> 2;           // sample local 0..1
    int chunk = warp & 3;         // ic chunk 0..3
    int s = blockIdx.x * 2 + sl;  // 0..79

    const float* xs = g_protos + (size_t)s * 1600;
    float2 acc[25];
    #pragma unroll
    for (int i = 0; i < 25; i++) acc[i] = make_float2(0.f, 0.f);

    #pragma unroll 1
    for (int icl = 0; icl < 16; icl++) {
        int ic = chunk * 16 + icl;
        const float2* wr = g_wp2 + ic * 288 + lane;
        float2 w[9];
        #pragma unroll
        for (int k = 0; k < 9; k++) w[k] = wr[k * 32];
        conv_ic(xs + ic * 25, w, acc);
    }

    float2* rb = red + (sl * HWSZ) * 32 + lane;
    if (chunk == 0) {
        #pragma unroll
        for (int p = 0; p < 25; p++) rb[p * 32] = acc[p];
    }
    __syncthreads();
    if (chunk == 1) {
        #pragma unroll
        for (int p = 0; p < 25; p++) {
            float2 t = rb[p * 32];
            t.x += acc[p].x; t.y += acc[p].y;
            rb[p * 32] = t;
        }
    }
    __syncthreads();
    if (chunk == 2) {
        #pragma unroll
        for (int p = 0; p < 25; p++) {
            float2 t = rb[p * 32];
            t.x += acc[p].x; t.y += acc[p].y;
            rb[p * 32] = t;
        }
    }
    __syncthreads();
    if (chunk == 3) {
        float2 sh = g_shift2[lane];
        #pragma unroll
        for (int p = 0; p < 25; p++) {
            float2 t = rb[p * 32];
            t.x += acc[p].x + sh.x;
            t.y += acc[p].y + sh.y;
            g_cp[(s * HWSZ + p) * 32 + lane] = t;
        }
    }
}

// ---------------- K2: conv on queries, warp-per-sample, smem weights ---------
// block = 256 threads = 8 warps = 8 samples; grid 300; weights staged 16 ics/chunk
__global__ void __launch_bounds__(256, 2) convq_kernel(const float* __restrict__ xq) {
    __shared__ __align__(16) float2 sw[16 * 9 * 32];   // 36.9 KB
    int tid = threadIdx.x;
    int lane = tid & 31;
    int warp = tid >> 5;
    int s = blockIdx.x * 8 + warp;                     // 0..2399
    const float* xs = xq + (size_t)s * 1600;

    float2 acc[25];
    #pragma unroll
    for (int i = 0; i < 25; i++) acc[i] = make_float2(0.f, 0.f);

    #pragma unroll 1
    for (int ch = 0; ch < 4; ch++) {
        __syncthreads();   // protect previous chunk's reads
        {
            const float4* src4 = (const float4*)(g_wq2 + ch * 16 * 288);
            float4* dst4 = (float4*)sw;
            #pragma unroll
            for (int i = 0; i < 9; i++)
                dst4[tid + i * 256] = src4[tid + i * 256];   // 2304 float4
        }
        __syncthreads();
        #pragma unroll 1
        for (int icl = 0; icl < 16; icl++) {
            const float2* wr = sw + icl * 288 + lane;
            float2 w[9];
            #pragma unroll
            for (int k = 0; k < 9; k++) w[k] = wr[k * 32];
            conv_ic(xs + (ch * 16 + icl) * 25, w, acc);
        }
    }

    // epilogue: combine with each proto, leaky, pool -> feat
    int b = s / NQ;
    #pragma unroll 1
    for (int w = 0; w < NWAY; w++) {
        const float2* cp = g_cp + ((b * NWAY + w) * HWSZ) * 32 + lane;
        float ax = 0.f, ay = 0.f;
        #pragma unroll
        for (int p = 0; p < 25; p++) {
            float2 c = cp[p * 32];
            float x = acc[p].x + c.x; x = fmaxf(x, LEAK * x);
            float y = acc[p].y + c.y; y = fmaxf(y, LEAK * y);
            ax += x; ay += y;
        }
        ((float2*)g_feat)[((size_t)s * NWAY + w) * 32 + lane] =
            make_float2(ax * 0.04f, ay * 0.04f);
    }
}

// ---------------- K3: relation MLP 64->300->1 + sigmoid ----------------------
// block = 320 threads, 48 rows/block, grid 250 (exactly one wave at 2/SM)
#define MROWS 48
__global__ void __launch_bounds__(320, 2) mlp_kernel(const float* __restrict__ w1,
                                                     const float* __restrict__ b1,
                                                     const float* __restrict__ w2,
                                                     const float* __restrict__ b2,
                                                     float* __restrict__ out) {
    __shared__ __align__(16) float smf[64][MROWS];   // 12.3 KB
    __shared__ float2 wsum[10][MROWS / 2];
    int s0 = blockIdx.x * MROWS;
    int tid = threadIdx.x;
    for (int i = tid; i < 64 * MROWS; i += 320) {
        int r = i / 64, c = i - (i / 64) * 64;
        smf[c][r] = g_feat[(size_t)(s0 + r) * CC + c];
    }
    __syncthreads();

    float2 po[MROWS / 2];
    #pragma unroll
    for (int rp = 0; rp < MROWS / 2; rp++) po[rp] = make_float2(0.f, 0.f);

    if (tid < NHID) {
        int j = tid;
        float2 acc[MROWS / 2];
        #pragma unroll
        for (int rp = 0; rp < MROWS / 2; rp++) acc[rp] = make_float2(0.f, 0.f);
        #pragma unroll 2
        for (int k = 0; k < 64; k++) {
            float wv = w1[k * NHID + j];
            float2 wv2 = make_float2(wv, wv);
            const float4* fr4 = (const float4*)smf[k];
            #pragma unroll
            for (int q = 0; q < MROWS / 4; q++) {
                float4 v = fr4[q];
                acc[2 * q]     = ffma2(make_float2(v.x, v.y), wv2, acc[2 * q]);
                acc[2 * q + 1] = ffma2(make_float2(v.z, v.w), wv2, acc[2 * q + 1]);
            }
        }
        float bj = b1[j], w2j = w2[j];
        #pragma unroll
        for (int rp = 0; rp < MROWS / 2; rp++) {
            float hx = acc[rp].x + bj; hx = fmaxf(hx, LEAK * hx);
            float hy = acc[rp].y + bj; hy = fmaxf(hy, LEAK * hy);
            po[rp] = make_float2(hx * w2j, hy * w2j);
        }
    }
    #pragma unroll
    for (int off = 16; off; off >>= 1) {
        #pragma unroll
        for (int rp = 0; rp < MROWS / 2; rp++) {
            po[rp].x += __shfl_down_sync(0xffffffffu, po[rp].x, off);
            po[rp].y += __shfl_down_sync(0xffffffffu, po[rp].y, off);
        }
    }
    int wid = tid >> 5, lid = tid & 31;
    if (lid == 0) {
        #pragma unroll
        for (int rp = 0; rp < MROWS / 2; rp++) wsum[wid][rp] = po[rp];
    }
    __syncthreads();
    if (tid < MROWS) {
        int rp = tid >> 1, half = tid & 1;
        float a = 0.f;
        #pragma unroll
        for (int w = 0; w < 10; w++)
            a += half ? wsum[w][rp].y : wsum[w][rp].x;
        a += b2[0];
        out[s0 + tid] = 1.f / (1.f + expf(-a));
    }
}

// ---------------- launch -----------------------------------------------------
extern "C" void kernel_launch(void* const* d_in, const int* in_sizes, int n_in,
                              void* d_out, int out_size) {
    const float* x_shot   = (const float*)d_in[0];
    const float* x_pseudo = (const float*)d_in[1];
    const float* x_query  = (const float*)d_in[2];
    const float* conv_w   = (const float*)d_in[3];
    const float* bn_gamma = (const float*)d_in[4];
    const float* bn_beta  = (const float*)d_in[5];
    const float* bn_mean  = (const float*)d_in[6];
    const float* bn_var   = (const float*)d_in[7];
    const float* w1       = (const float*)d_in[8];
    const float* b1       = (const float*)d_in[9];
    const float* w2       = (const float*)d_in[10];
    const float* b2       = (const float*)d_in[11];
    float* out = (float*)d_out;

    prep_protos_kernel<<<PREP_BLOCKS + PROTO_BLOCKS, 256>>>(
        conv_w, bn_gamma, bn_beta, bn_mean, bn_var, x_shot, x_pseudo);
    convp_kernel<<<NSAMP_P / 2, 256>>>();
    convq_kernel<<<NSAMP_Q / 8, 256>>>(x_query);
    mlp_kernel<<<NPAIR / MROWS, 320>>>(w1, b1, w2, b2, out);
}